// round 2
// baseline (speedup 1.0000x reference)
#include <cuda_runtime.h>
#include <cstdint>

// LogicalConsistencyLoss: out = 0.5 * (S_lin + S_abs) / (R*B)
//   S_abs = sum_{s,a,b,c} |M_ab - M_ac*M_bc|
//   S_lin = sum_s [ N * sum(M) - sum_c (colsum_c)^2 ]
// where M = sigmoid(logits) * mask_a * mask_b per (batch, relation) slice.
// Cubic pass uses packed f32x2 FMA/ADD (fma pipe) + and.b64 abs (alu pipe).

#define B_ 2
#define N_ 512
#define R_ 4
#define S_ (B_ * R_)                   // 8 slices
#define NT (N_ / 128)                  // 4 tiles per dim
#define CSPLIT 4
#define NPART (NT * NT * CSPLIT * S_)  // 512 cubic partials
#define LINB (S_ * 4)                  // 32 colsum partial blocks

__device__ float  g_rel[S_ * N_ * N_];   // 8 MB scratch: [slice][a][b]
__device__ float  g_part[NPART];
__device__ double g_lin1[LINB];          // partial sum of colsums (= partial sum(M))
__device__ double g_lin2[LINB];          // partial sum of colsum^2

// ---- packed f32x2 helpers (ptxas never emits these from C++) ----
__device__ __forceinline__ uint64_t fma2(uint64_t a, uint64_t b, uint64_t c) {
    uint64_t d;
    asm("fma.rn.f32x2 %0, %1, %2, %3;" : "=l"(d) : "l"(a), "l"(b), "l"(c));
    return d;
}
__device__ __forceinline__ uint64_t add2(uint64_t a, uint64_t b) {
    uint64_t d;
    asm("add.rn.f32x2 %0, %1, %2;" : "=l"(d) : "l"(a), "l"(b));
    return d;
}

// ---------------- Pass 1: sigmoid + mask, de-interleave R ----------------
__global__ void sigmoid_mask_kernel(const float* __restrict__ logits,
                                    const int*   __restrict__ masks) {
    int idx = blockIdx.x * blockDim.x + threadIdx.x;  // over B*N*N
    if (idx >= B_ * N_ * N_) return;
    int b   = idx / (N_ * N_);
    int rem = idx - b * (N_ * N_);
    int i   = rem / N_;
    int j   = rem - i * N_;
    float mm = (masks[b * N_ + i] > 0 && masks[b * N_ + j] > 0) ? 1.0f : 0.0f;
    float4 v = ((const float4*)logits)[idx];  // 4 relations of one (b,i,j)
    float p0 = mm / (1.0f + __expf(-v.x));
    float p1 = mm / (1.0f + __expf(-v.y));
    float p2 = mm / (1.0f + __expf(-v.z));
    float p3 = mm / (1.0f + __expf(-v.w));
    g_rel[(b * R_ + 0) * N_ * N_ + rem] = p0;
    g_rel[(b * R_ + 1) * N_ * N_ + rem] = p1;
    g_rel[(b * R_ + 2) * N_ * N_ + rem] = p2;
    g_rel[(b * R_ + 3) * N_ * N_ + rem] = p3;
}

// ---------------- Pass 2: cubic |.| contraction, packed f32x2 ----------------
// Grid: x = (a,b) tile (16), y = c-split (4), z = slice (8). 256 threads.
// Each thread: 8x8 register tile of M_ab (packed as 8x4 u64), 8 packed accs.
__global__ void __launch_bounds__(256, 2)
trans_abs_kernel() {
    const int tile = blockIdx.x;      // 0..15
    const int cblk = blockIdx.y;      // 0..3
    const int sl   = blockIdx.z;      // 0..7
    const float* __restrict__ M = g_rel + sl * N_ * N_;

    const int a0 = (tile / NT) * 128;
    const int b0 = (tile % NT) * 128;
    const int c0 = cblk * (N_ / CSPLIT);

    const int tid = threadIdx.x;
    const int tx  = tid & 15;         // b sub-tile
    const int ty  = tid >> 4;         // a sub-tile

    // Load 8x8 M_ab register tile, packed as (j,j+1) pairs in u64.
    uint64_t mab2[8][4];
#pragma unroll
    for (int i = 0; i < 8; ++i) {
        const ulonglong2* row =
            (const ulonglong2*)(M + (a0 + ty * 8 + i) * N_ + b0 + tx * 8);
        ulonglong2 q0 = row[0];
        ulonglong2 q1 = row[1];
        mab2[i][0] = q0.x; mab2[i][1] = q0.y;
        mab2[i][2] = q1.x; mab2[i][3] = q1.y;
    }

    // sA: NEGATED and DUPLICATED: sA[c][2a]=sA[c][2a+1] = -M[a0+a][c]
    // so an LDS.128 yields two packed {-a,-a} broadcast pairs directly.
    __shared__ float sA[8][256];
    __shared__ float sB[8][128];

    uint64_t acc2[8];
#pragma unroll
    for (int p = 0; p < 8; ++p) acc2[p] = 0ULL;

    const int r   = tid >> 1;         // 0..127: row within tile to stage
    const int cof = (tid & 1) * 4;    // which 4 c's

    for (int cc = c0; cc < c0 + N_ / CSPLIT; cc += 8) {
        float4 va = *(const float4*)(M + (a0 + r) * N_ + cc + cof);
        float4 vb = *(const float4*)(M + (b0 + r) * N_ + cc + cof);
        __syncthreads();   // previous chunk's compute done before overwrite
        *(float2*)&sA[cof + 0][2 * r] = make_float2(-va.x, -va.x);
        *(float2*)&sA[cof + 1][2 * r] = make_float2(-va.y, -va.y);
        *(float2*)&sA[cof + 2][2 * r] = make_float2(-va.z, -va.z);
        *(float2*)&sA[cof + 3][2 * r] = make_float2(-va.w, -va.w);
        sB[cof + 0][r] = vb.x; sB[cof + 1][r] = vb.y;
        sB[cof + 2][r] = vb.z; sB[cof + 3][r] = vb.w;
        __syncthreads();

#pragma unroll
        for (int c = 0; c < 8; ++c) {
            // 8 packed {-a,-a} pairs: 4 x LDS.128
            const ulonglong2* pa = (const ulonglong2*)&sA[c][ty * 16];
            // 4 packed {b_j,b_{j+1}} pairs: 2 x LDS.128
            const ulonglong2* pb = (const ulonglong2*)&sB[c][tx * 8];
            ulonglong2 B0 = pb[0], B1 = pb[1];
            uint64_t nb[4] = {B0.x, B0.y, B1.x, B1.y};

#pragma unroll
            for (int ih = 0; ih < 2; ++ih) {     // halves of i to limit live regs
                ulonglong2 A0 = pa[2 * ih + 0];
                ulonglong2 A1 = pa[2 * ih + 1];
                uint64_t na[4] = {A0.x, A0.y, A1.x, A1.y};
#pragma unroll
                for (int ii = 0; ii < 4; ++ii) {
                    const int pbase = (ii & 1) * 4;
#pragma unroll
                    for (int jp = 0; jp < 4; ++jp) {
                        uint64_t t = fma2(na[ii], nb[jp], mab2[ih * 4 + ii][jp]);
                        t &= 0x7FFFFFFF7FFFFFFFULL;          // |.|x2 : 2 LOP3 (alu pipe)
                        acc2[pbase + jp] = add2(acc2[pbase + jp], t);
                    }
                }
            }
        }
    }

    // Unpack + deterministic block reduction.
    float tsum = 0.0f;
#pragma unroll
    for (int p = 0; p < 8; ++p) {
        tsum += __uint_as_float((uint32_t)acc2[p]);
        tsum += __uint_as_float((uint32_t)(acc2[p] >> 32));
    }
#pragma unroll
    for (int off = 16; off > 0; off >>= 1)
        tsum += __shfl_down_sync(0xFFFFFFFFu, tsum, off);

    __shared__ float wred[8];
    if ((tid & 31) == 0) wred[tid >> 5] = tsum;
    __syncthreads();
    if (tid == 0) {
        float s = 0.0f;
#pragma unroll
        for (int w = 0; w < 8; ++w) s += wred[w];
        g_part[(sl * CSPLIT + cblk) * (NT * NT) + tile] = s;
    }
}

// ---------------- Pass 3: linear correction, 32 blocks ----------------
// grid (S_, 4), 128 threads: block handles 128 columns of one slice.
__global__ void colsum_kernel() {
    const int sl = blockIdx.x;
    const int c  = blockIdx.y * 128 + threadIdx.x;
    const float* __restrict__ M = g_rel + sl * N_ * N_;
    float s = 0.0f;
#pragma unroll 8
    for (int a = 0; a < N_; ++a) s += M[a * N_ + c];

    double s1 = (double)s;
    double s2 = (double)s * (double)s;
#pragma unroll
    for (int off = 16; off > 0; off >>= 1) {
        s1 += __shfl_down_sync(0xFFFFFFFFu, s1, off);
        s2 += __shfl_down_sync(0xFFFFFFFFu, s2, off);
    }
    __shared__ double w1[4], w2[4];
    const int lane = threadIdx.x & 31, warp = threadIdx.x >> 5;
    if (lane == 0) { w1[warp] = s1; w2[warp] = s2; }
    __syncthreads();
    if (threadIdx.x == 0) {
        double t1 = 0.0, t2 = 0.0;
#pragma unroll
        for (int w = 0; w < 4; ++w) { t1 += w1[w]; t2 += w2[w]; }
        g_lin1[sl * 4 + blockIdx.y] = t1;
        g_lin2[sl * 4 + blockIdx.y] = t2;
    }
}

// ---------------- Pass 4: deterministic final combine ----------------
__global__ void final_kernel(float* __restrict__ out) {
    const int t = threadIdx.x;  // 256
    double s = (double)g_part[t] + (double)g_part[t + 256];
#pragma unroll
    for (int off = 16; off > 0; off >>= 1)
        s += __shfl_down_sync(0xFFFFFFFFu, s, off);
    __shared__ double w[8];
    if ((t & 31) == 0) w[t >> 5] = s;
    __syncthreads();
    if (t == 0) {
        double sabs = 0.0;
#pragma unroll
        for (int k = 0; k < 8; ++k) sabs += w[k];
        double l1 = 0.0, l2 = 0.0;
#pragma unroll
        for (int k = 0; k < LINB; ++k) { l1 += g_lin1[k]; l2 += g_lin2[k]; }
        double slin = (double)N_ * l1 - l2;
        out[0] = (float)(0.5 * (sabs + slin) / (double)(R_ * B_));
    }
}

extern "C" void kernel_launch(void* const* d_in, const int* in_sizes, int n_in,
                              void* d_out, int out_size) {
    const float* logits = (const float*)d_in[0];
    const int*   masks  = (const int*)d_in[1];
    float*       out    = (float*)d_out;

    sigmoid_mask_kernel<<<(B_ * N_ * N_ + 255) / 256, 256>>>(logits, masks);

    dim3 g2(NT * NT, CSPLIT, S_);
    trans_abs_kernel<<<g2, 256>>>();

    dim3 g3(S_, 4);
    colsum_kernel<<<g3, 128>>>();
    final_kernel<<<1, 256>>>(out);
}

// round 3
// speedup vs baseline: 1.5598x; 1.5598x over previous
#include <cuda_runtime.h>
#include <cuda_fp16.h>
#include <cstdint>

// LogicalConsistencyLoss: out = 0.5 * (S_lin + S_abs) / (R*B)
//   S_abs = sum_{s,a,b,c} |M_ab - M_ac*M_bc|    (fp16x2 HFMA2/HADD2 path)
//   S_lin = sum_s [ N * sum(M) - sum_c (colsum_c)^2 ]
// where M = fp16(sigmoid(logits)) * mask_a * mask_b per (batch,relation) slice.
// Using the SAME quantized M in both terms keeps the relu identity exact.

#define B_ 2
#define N_ 512
#define R_ 4
#define S_ (B_ * R_)                   // 8 slices
#define NT (N_ / 128)                  // 4 tiles per dim
#define CS 16                          // c-split
#define NPART (NT * NT * CS * S_)      // 2048 cubic partials
#define LINB (S_ * 4)                  // 32 colsum partial blocks

__device__ __half  g_relh[S_ * N_ * N_];   // 4 MB scratch (L2-resident)
__device__ float   g_part[NPART];
__device__ double  g_lin1[LINB];
__device__ double  g_lin2[LINB];

__device__ __forceinline__ __half2 habs2_(__half2 x) {
    uint32_t u = *reinterpret_cast<uint32_t*>(&x) & 0x7FFF7FFFu;  // 1 LOP3 (alu)
    return *reinterpret_cast<__half2*>(&u);
}

// ---------------- Pass 1: sigmoid + mask -> fp16, de-interleave R ----------------
__global__ void sigmoid_mask_kernel(const float* __restrict__ logits,
                                    const int*   __restrict__ masks) {
    int idx = blockIdx.x * blockDim.x + threadIdx.x;  // over B*N*N
    if (idx >= B_ * N_ * N_) return;
    int b   = idx / (N_ * N_);
    int rem = idx - b * (N_ * N_);
    int i   = rem / N_;
    int j   = rem - i * N_;
    float mm = (masks[b * N_ + i] > 0 && masks[b * N_ + j] > 0) ? 1.0f : 0.0f;
    float4 v = ((const float4*)logits)[idx];  // 4 relations of one (b,i,j)
    float p0 = __fdividef(mm, 1.0f + __expf(-v.x));
    float p1 = __fdividef(mm, 1.0f + __expf(-v.y));
    float p2 = __fdividef(mm, 1.0f + __expf(-v.z));
    float p3 = __fdividef(mm, 1.0f + __expf(-v.w));
    g_relh[(b * R_ + 0) * N_ * N_ + rem] = __float2half(p0);
    g_relh[(b * R_ + 1) * N_ * N_ + rem] = __float2half(p1);
    g_relh[(b * R_ + 2) * N_ * N_ + rem] = __float2half(p2);
    g_relh[(b * R_ + 3) * N_ * N_ + rem] = __float2half(p3);
}

// ---------------- Pass 2: cubic |.| contraction, HFMA2 ----------------
// Grid: x = (a,b) tile (16), y = c-split (16), z = slice (8). 256 threads.
// Thread: 8x8 fp16 M_ab tile as 8x4 half2 regs; 4 half2 chunk accs -> 8 f32.
__global__ void __launch_bounds__(256, 2)
trans_abs_kernel() {
    const int tile = blockIdx.x;      // 0..15
    const int cblk = blockIdx.y;      // 0..15
    const int sl   = blockIdx.z;      // 0..7
    const __half* __restrict__ M = g_relh + sl * N_ * N_;

    const int a0 = (tile / NT) * 128;
    const int b0 = (tile % NT) * 128;
    const int c0 = cblk * (N_ / CS);  // 32 c's per CTA

    const int tid = threadIdx.x;
    const int tx  = tid & 15;         // b sub-tile
    const int ty  = tid >> 4;         // a sub-tile

    // 8x8 M_ab tile packed as half2 (j,j+1) pairs: 32 regs.
    __half2 mab2[8][4];
#pragma unroll
    for (int i = 0; i < 8; ++i) {
        uint4 q = *(const uint4*)(M + (a0 + ty * 8 + i) * N_ + b0 + tx * 8);
        mab2[i][0] = *(__half2*)&q.x; mab2[i][1] = *(__half2*)&q.y;
        mab2[i][2] = *(__half2*)&q.z; mab2[i][3] = *(__half2*)&q.w;
    }

    // sA holds NEGATED + DUPLICATED values: sA[c][2a]=sA[c][2a+1] = -M[a0+a][c]
    // so uint4 LDS yields 4 ready {-a,-a} half2 broadcast pairs.
    __shared__ __align__(16) __half sA[8][256];   // 4 KB
    __shared__ __align__(16) __half sB[8][128];   // 2 KB

    float facc[8];
#pragma unroll
    for (int p = 0; p < 8; ++p) facc[p] = 0.0f;

    const int  sr  = tid & 127;       // staging row within tile
    const bool isB = tid >= 128;

    for (int cc = c0; cc < c0 + N_ / CS; cc += 8) {
        // stage 8 c-values of one A-row or one B-row
        uint4 v = *(const uint4*)(M + ((isB ? b0 : a0) + sr) * N_ + cc);
        __syncthreads();   // previous chunk's compute done before overwrite
        const __half* vh = (const __half*)&v;
        if (!isB) {
#pragma unroll
            for (int k = 0; k < 8; ++k) {
                __half2 p = __half2half2(__hneg(vh[k]));
                *(uint32_t*)&sA[k][2 * sr] = *(uint32_t*)&p;
            }
        } else {
#pragma unroll
            for (int k = 0; k < 8; ++k) sB[k][sr] = vh[k];
        }
        __syncthreads();

        __half2 hz = __float2half2_rn(0.0f);
        __half2 hacc[4] = {hz, hz, hz, hz};       // <=64 terms/chunk, range OK

#pragma unroll
        for (int c = 0; c < 8; ++c) {
            uint4 A0 = *(const uint4*)&sA[c][ty * 16];
            uint4 A1 = *(const uint4*)&sA[c][ty * 16 + 8];
            uint4 Bv = *(const uint4*)&sB[c][tx * 8];
            __half2 a2[8], b2[4];
            a2[0] = *(__half2*)&A0.x; a2[1] = *(__half2*)&A0.y;
            a2[2] = *(__half2*)&A0.z; a2[3] = *(__half2*)&A0.w;
            a2[4] = *(__half2*)&A1.x; a2[5] = *(__half2*)&A1.y;
            a2[6] = *(__half2*)&A1.z; a2[7] = *(__half2*)&A1.w;
            b2[0] = *(__half2*)&Bv.x; b2[1] = *(__half2*)&Bv.y;
            b2[2] = *(__half2*)&Bv.z; b2[3] = *(__half2*)&Bv.w;
#pragma unroll
            for (int i = 0; i < 8; ++i) {
#pragma unroll
                for (int jp = 0; jp < 4; ++jp) {
                    // HFMA2 (fma pipe) + LOP3 abs (alu pipe) + HADD2 (fma pipe)
                    __half2 t = __hfma2(a2[i], b2[jp], mab2[i][jp]);
                    hacc[jp] = __hadd2(hacc[jp], habs2_(t));
                }
            }
        }

        // promote chunk accumulators to fp32 (3% overhead)
#pragma unroll
        for (int jp = 0; jp < 4; ++jp) {
            facc[2 * jp]     += __low2float(hacc[jp]);
            facc[2 * jp + 1] += __high2float(hacc[jp]);
        }
    }

    // Deterministic block reduction.
    float tsum = 0.0f;
#pragma unroll
    for (int p = 0; p < 8; ++p) tsum += facc[p];
#pragma unroll
    for (int off = 16; off > 0; off >>= 1)
        tsum += __shfl_down_sync(0xFFFFFFFFu, tsum, off);

    __shared__ float wred[8];
    if ((tid & 31) == 0) wred[tid >> 5] = tsum;
    __syncthreads();
    if (tid == 0) {
        float s = 0.0f;
#pragma unroll
        for (int w = 0; w < 8; ++w) s += wred[w];
        g_part[(sl * CS + cblk) * (NT * NT) + tile] = s;
    }
}

// ---------------- Pass 3: linear correction, 32 blocks ----------------
__global__ void colsum_kernel() {
    const int sl = blockIdx.x;
    const int c  = blockIdx.y * 128 + threadIdx.x;
    const __half* __restrict__ M = g_relh + sl * N_ * N_;
    float s = 0.0f;
#pragma unroll 8
    for (int a = 0; a < N_; ++a) s += __half2float(M[a * N_ + c]);

    double s1 = (double)s;
    double s2 = (double)s * (double)s;
#pragma unroll
    for (int off = 16; off > 0; off >>= 1) {
        s1 += __shfl_down_sync(0xFFFFFFFFu, s1, off);
        s2 += __shfl_down_sync(0xFFFFFFFFu, s2, off);
    }
    __shared__ double w1[4], w2[4];
    const int lane = threadIdx.x & 31, warp = threadIdx.x >> 5;
    if (lane == 0) { w1[warp] = s1; w2[warp] = s2; }
    __syncthreads();
    if (threadIdx.x == 0) {
        double t1 = 0.0, t2 = 0.0;
#pragma unroll
        for (int w = 0; w < 4; ++w) { t1 += w1[w]; t2 += w2[w]; }
        g_lin1[sl * 4 + blockIdx.y] = t1;
        g_lin2[sl * 4 + blockIdx.y] = t2;
    }
}

// ---------------- Pass 4: deterministic final combine ----------------
__global__ void final_kernel(float* __restrict__ out) {
    const int t = threadIdx.x;  // 512
    double s = 0.0;
#pragma unroll
    for (int k = 0; k < NPART / 512; ++k) s += (double)g_part[t + k * 512];
#pragma unroll
    for (int off = 16; off > 0; off >>= 1)
        s += __shfl_down_sync(0xFFFFFFFFu, s, off);
    __shared__ double w[16];
    if ((t & 31) == 0) w[t >> 5] = s;
    __syncthreads();
    if (t == 0) {
        double sabs = 0.0;
#pragma unroll
        for (int k = 0; k < 16; ++k) sabs += w[k];
        double l1 = 0.0, l2 = 0.0;
#pragma unroll
        for (int k = 0; k < LINB; ++k) { l1 += g_lin1[k]; l2 += g_lin2[k]; }
        double slin = (double)N_ * l1 - l2;
        out[0] = (float)(0.5 * (sabs + slin) / (double)(R_ * B_));
    }
}

extern "C" void kernel_launch(void* const* d_in, const int* in_sizes, int n_in,
                              void* d_out, int out_size) {
    const float* logits = (const float*)d_in[0];
    const int*   masks  = (const int*)d_in[1];
    float*       out    = (float*)d_out;

    sigmoid_mask_kernel<<<(B_ * N_ * N_ + 255) / 256, 256>>>(logits, masks);

    dim3 g2(NT * NT, CS, S_);
    trans_abs_kernel<<<g2, 256>>>();

    dim3 g3(S_, 4);
    colsum_kernel<<<g3, 128>>>();
    final_kernel<<<1, 512>>>(out);
}

// round 4
// speedup vs baseline: 1.8607x; 1.1929x over previous
#include <cuda_runtime.h>
#include <cuda_fp16.h>
#include <cstdint>

// LogicalConsistencyLoss: out = sum_{s,a,b,c} relu(M_ab - M_ac*M_bc) / (R*B)
// where M = fp16(sigmoid(logits)) * mask_a * mask_b per (batch,relation) slice.
// Direct relu via HMNMX2 (alu pipe) -> no linear-correction pass needed.
// Final reduction fused into the last cubic CTA (threadfence pattern).

#define B_ 2
#define N_ 512
#define R_ 4
#define S_ (B_ * R_)                   // 8 slices
#define NT (N_ / 128)                  // 4 tiles per dim
#define CS 16                          // c-split
#define NCTA (NT * NT * CS * S_)       // 2048 cubic CTAs / partials

__device__ __half    g_relh[S_ * N_ * N_];   // 4 MB scratch (L2-resident)
__device__ float     g_part[NCTA];
__device__ unsigned  g_ctr;                  // zero-init; reset by last CTA

__device__ __forceinline__ __half2 hmax2_(__half2 a, __half2 b) {
#if __CUDA_ARCH__ >= 800
    return __hmax2(a, b);
#else
    return a;
#endif
}

// ---------------- Pass 1: sigmoid + mask -> fp16, de-interleave R ----------------
__global__ void sigmoid_mask_kernel(const float* __restrict__ logits,
                                    const int*   __restrict__ masks) {
    int idx = blockIdx.x * blockDim.x + threadIdx.x;  // over B*N*N
    if (idx >= B_ * N_ * N_) return;
    int b   = idx / (N_ * N_);
    int rem = idx - b * (N_ * N_);
    int i   = rem / N_;
    int j   = rem - i * N_;
    float mm = (masks[b * N_ + i] > 0 && masks[b * N_ + j] > 0) ? 1.0f : 0.0f;
    float4 v = ((const float4*)logits)[idx];  // 4 relations of one (b,i,j)
    float p0 = __fdividef(mm, 1.0f + __expf(-v.x));
    float p1 = __fdividef(mm, 1.0f + __expf(-v.y));
    float p2 = __fdividef(mm, 1.0f + __expf(-v.z));
    float p3 = __fdividef(mm, 1.0f + __expf(-v.w));
    g_relh[(b * R_ + 0) * N_ * N_ + rem] = __float2half(p0);
    g_relh[(b * R_ + 1) * N_ * N_ + rem] = __float2half(p1);
    g_relh[(b * R_ + 2) * N_ * N_ + rem] = __float2half(p2);
    g_relh[(b * R_ + 3) * N_ * N_ + rem] = __float2half(p3);
}

// ---------------- Pass 2: cubic relu contraction + fused final reduce ----------
// Grid: x = (a,b) tile (16), y = c-split (16), z = slice (8). 256 threads.
// Thread: 8x8 fp16 M_ab tile as 8x4 half2 regs; 8 half2 chunk accs -> 8 f32.
__global__ void __launch_bounds__(256, 2)
trans_relu_kernel(float* __restrict__ out) {
    const int tile = blockIdx.x;      // 0..15
    const int cblk = blockIdx.y;      // 0..15
    const int sl   = blockIdx.z;      // 0..7
    const __half* __restrict__ M = g_relh + sl * N_ * N_;

    const int a0 = (tile / NT) * 128;
    const int b0 = (tile % NT) * 128;
    const int c0 = cblk * (N_ / CS);  // 32 c's per CTA

    const int tid = threadIdx.x;
    const int tx  = tid & 15;         // b sub-tile
    const int ty  = tid >> 4;         // a sub-tile

    // 8x8 M_ab tile packed as half2 (j,j+1) pairs: 32 regs.
    __half2 mab2[8][4];
#pragma unroll
    for (int i = 0; i < 8; ++i) {
        uint4 q = *(const uint4*)(M + (a0 + ty * 8 + i) * N_ + b0 + tx * 8);
        mab2[i][0] = *(__half2*)&q.x; mab2[i][1] = *(__half2*)&q.y;
        mab2[i][2] = *(__half2*)&q.z; mab2[i][3] = *(__half2*)&q.w;
    }

    // sA holds NEGATED + DUPLICATED values: sA[c][2a]=sA[c][2a+1] = -M[a0+a][c]
    // so uint4 LDS yields 4 ready {-a,-a} half2 broadcast pairs.
    __shared__ __align__(16) __half sA[8][256];   // 4 KB
    __shared__ __align__(16) __half sB[8][128];   // 2 KB

    float facc[8];
#pragma unroll
    for (int p = 0; p < 8; ++p) facc[p] = 0.0f;

    const int  sr  = tid & 127;       // staging row within tile
    const bool isB = tid >= 128;

    const __half2 hz = __float2half2_rn(0.0f);

    for (int cc = c0; cc < c0 + N_ / CS; cc += 8) {
        // stage 8 c-values of one A-row or one B-row
        uint4 v = *(const uint4*)(M + ((isB ? b0 : a0) + sr) * N_ + cc);
        __syncthreads();   // previous chunk's compute done before overwrite
        const __half* vh = (const __half*)&v;
        if (!isB) {
#pragma unroll
            for (int k = 0; k < 8; ++k) {
                __half2 p = __half2half2(__hneg(vh[k]));
                *(uint32_t*)&sA[k][2 * sr] = *(uint32_t*)&p;
            }
        } else {
#pragma unroll
            for (int k = 0; k < 8; ++k) sB[k][sr] = vh[k];
        }
        __syncthreads();

        __half2 hacc[8];                   // per-i accs: <=32 terms each
#pragma unroll
        for (int i = 0; i < 8; ++i) hacc[i] = hz;

#pragma unroll
        for (int c = 0; c < 8; ++c) {
            uint4 A0 = *(const uint4*)&sA[c][ty * 16];
            uint4 A1 = *(const uint4*)&sA[c][ty * 16 + 8];
            uint4 Bv = *(const uint4*)&sB[c][tx * 8];
            __half2 a2[8], b2[4];
            a2[0] = *(__half2*)&A0.x; a2[1] = *(__half2*)&A0.y;
            a2[2] = *(__half2*)&A0.z; a2[3] = *(__half2*)&A0.w;
            a2[4] = *(__half2*)&A1.x; a2[5] = *(__half2*)&A1.y;
            a2[6] = *(__half2*)&A1.z; a2[7] = *(__half2*)&A1.w;
            b2[0] = *(__half2*)&Bv.x; b2[1] = *(__half2*)&Bv.y;
            b2[2] = *(__half2*)&Bv.z; b2[3] = *(__half2*)&Bv.w;
#pragma unroll
            for (int i = 0; i < 8; ++i) {
#pragma unroll
                for (int jp = 0; jp < 4; ++jp) {
                    // HFMA2 (fma) + HMNMX2 relu (alu) + HADD2 (fma)
                    __half2 t = __hfma2(a2[i], b2[jp], mab2[i][jp]);
                    hacc[i] = __hadd2(hacc[i], hmax2_(t, hz));
                }
            }
        }

        // promote chunk accumulators to fp32
#pragma unroll
        for (int i = 0; i < 8; ++i) {
            facc[i & 7] += __low2float(hacc[i]);
            facc[i & 7] += __high2float(hacc[i]);
        }
    }

    // Deterministic block reduction.
    float tsum = 0.0f;
#pragma unroll
    for (int p = 0; p < 8; ++p) tsum += facc[p];
#pragma unroll
    for (int off = 16; off > 0; off >>= 1)
        tsum += __shfl_down_sync(0xFFFFFFFFu, tsum, off);

    __shared__ float wred[8];
    if ((tid & 31) == 0) wred[tid >> 5] = tsum;
    __syncthreads();

    // Publish partial, then elect the last-finishing CTA to do the final sum.
    __shared__ bool amLast;
    if (tid == 0) {
        float s = 0.0f;
#pragma unroll
        for (int w = 0; w < 8; ++w) s += wred[w];
        const int part = ((sl * CS + cblk) * (NT * NT)) + tile;
        g_part[part] = s;
        __threadfence();
        unsigned ticket = atomicAdd(&g_ctr, 1u);
        amLast = (ticket == NCTA - 1);
    }
    __syncthreads();

    if (amLast) {
        // Fixed-order deterministic final reduce over all 2048 partials.
        double s = 0.0;
#pragma unroll
        for (int k = 0; k < NCTA / 256; ++k)
            s += (double)g_part[tid + k * 256];
#pragma unroll
        for (int off = 16; off > 0; off >>= 1)
            s += __shfl_down_sync(0xFFFFFFFFu, s, off);
        __shared__ double dw[8];
        if ((tid & 31) == 0) dw[tid >> 5] = s;
        __syncthreads();
        if (tid == 0) {
            double tot = 0.0;
#pragma unroll
            for (int w = 0; w < 8; ++w) tot += dw[w];
            out[0] = (float)(tot / (double)(R_ * B_));
            g_ctr = 0;   // reset for next graph replay
        }
    }
}

extern "C" void kernel_launch(void* const* d_in, const int* in_sizes, int n_in,
                              void* d_out, int out_size) {
    const float* logits = (const float*)d_in[0];
    const int*   masks  = (const int*)d_in[1];
    float*       out    = (float*)d_out;

    sigmoid_mask_kernel<<<(B_ * N_ * N_ + 255) / 256, 256>>>(logits, masks);

    dim3 g2(NT * NT, CS, S_);
    trans_relu_kernel<<<g2, 256>>>(out);
}

// round 5
// speedup vs baseline: 1.9630x; 1.0550x over previous
#include <cuda_runtime.h>
#include <cuda_fp16.h>
#include <cstdint>

// LogicalConsistencyLoss: out = sum_{s,a,b,c} relu(M_ab - M_ac*M_bc) / (R*B)
// where M = fp16(sigmoid(logits)) * mask_a * mask_b per (batch,relation) slice.
// Direct relu via HMNMX2 (alu pipe). Final reduction fused into last CTA.
// R5: occupancy 2->3 CTAs/SM (register diet + launch_bounds(256,3)).

#define B_ 2
#define N_ 512
#define R_ 4
#define S_ (B_ * R_)                   // 8 slices
#define NT (N_ / 128)                  // 4 tiles per dim
#define CS 16                          // c-split
#define NCTA (NT * NT * CS * S_)       // 2048 cubic CTAs / partials

__device__ __half    g_relh[S_ * N_ * N_];   // 4 MB scratch (L2-resident)
__device__ float     g_part[NCTA];
__device__ unsigned  g_ctr;                  // zero-init; reset by last CTA

// ---------------- Pass 1: sigmoid + mask -> fp16, de-interleave R ----------------
__global__ void sigmoid_mask_kernel(const float* __restrict__ logits,
                                    const int*   __restrict__ masks) {
    int idx = blockIdx.x * blockDim.x + threadIdx.x;  // over B*N*N
    if (idx >= B_ * N_ * N_) return;
    int b   = idx / (N_ * N_);
    int rem = idx - b * (N_ * N_);
    int i   = rem / N_;
    int j   = rem - i * N_;
    float mm = (masks[b * N_ + i] > 0 && masks[b * N_ + j] > 0) ? 1.0f : 0.0f;
    float4 v = ((const float4*)logits)[idx];  // 4 relations of one (b,i,j)
    float p0 = __fdividef(mm, 1.0f + __expf(-v.x));
    float p1 = __fdividef(mm, 1.0f + __expf(-v.y));
    float p2 = __fdividef(mm, 1.0f + __expf(-v.z));
    float p3 = __fdividef(mm, 1.0f + __expf(-v.w));
    g_relh[(b * R_ + 0) * N_ * N_ + rem] = __float2half(p0);
    g_relh[(b * R_ + 1) * N_ * N_ + rem] = __float2half(p1);
    g_relh[(b * R_ + 2) * N_ * N_ + rem] = __float2half(p2);
    g_relh[(b * R_ + 3) * N_ * N_ + rem] = __float2half(p3);
}

// ---------------- Pass 2: cubic relu contraction + fused final reduce ----------
// Grid: x = (a,b) tile (16), y = c-split (16), z = slice (8). 256 threads.
// Thread: 8x8 fp16 M_ab tile as 8x4 half2 regs; 8 half2 chunk accs -> 4 f32.
__global__ void __launch_bounds__(256, 3)
trans_relu_kernel(float* __restrict__ out) {
    const int tile = blockIdx.x;      // 0..15
    const int cblk = blockIdx.y;      // 0..15
    const int sl   = blockIdx.z;      // 0..7
    const __half* __restrict__ M = g_relh + sl * N_ * N_;

    const int a0 = (tile / NT) * 128;
    const int b0 = (tile % NT) * 128;
    const int c0 = cblk * (N_ / CS);  // 32 c's per CTA

    const int tid = threadIdx.x;
    const int tx  = tid & 15;         // b sub-tile
    const int ty  = tid >> 4;         // a sub-tile

    // 8x8 M_ab tile packed as half2 (j,j+1) pairs: 32 regs.
    __half2 mab2[8][4];
#pragma unroll
    for (int i = 0; i < 8; ++i) {
        uint4 q = *(const uint4*)(M + (a0 + ty * 8 + i) * N_ + b0 + tx * 8);
        mab2[i][0] = *(__half2*)&q.x; mab2[i][1] = *(__half2*)&q.y;
        mab2[i][2] = *(__half2*)&q.z; mab2[i][3] = *(__half2*)&q.w;
    }

    // sA holds NEGATED + DUPLICATED values: sA[c][2a]=sA[c][2a+1] = -M[a0+a][c]
    // so uint4 LDS yields 4 ready {-a,-a} half2 broadcast pairs.
    __shared__ __align__(16) __half sA[8][256];   // 4 KB
    __shared__ __align__(16) __half sB[8][128];   // 2 KB

    float facc[4];
#pragma unroll
    for (int p = 0; p < 4; ++p) facc[p] = 0.0f;

    const int  sr  = tid & 127;       // staging row within tile
    const bool isB = tid >= 128;

    const __half2 hz = __float2half2_rn(0.0f);

    for (int cc = c0; cc < c0 + N_ / CS; cc += 8) {
        // stage 8 c-values of one A-row or one B-row
        uint4 v = *(const uint4*)(M + ((isB ? b0 : a0) + sr) * N_ + cc);
        __syncthreads();   // previous chunk's compute done before overwrite
        const __half* vh = (const __half*)&v;
        if (!isB) {
#pragma unroll
            for (int k = 0; k < 8; ++k) {
                __half2 p = __half2half2(__hneg(vh[k]));
                *(uint32_t*)&sA[k][2 * sr] = *(uint32_t*)&p;
            }
        } else {
#pragma unroll
            for (int k = 0; k < 8; ++k) sB[k][sr] = vh[k];
        }
        __syncthreads();

        __half2 hacc[8];                   // per-i accs: <=32 terms each
#pragma unroll
        for (int i = 0; i < 8; ++i) hacc[i] = hz;

#pragma unroll
        for (int c = 0; c < 8; ++c) {
            uint4 A0 = *(const uint4*)&sA[c][ty * 16];
            uint4 A1 = *(const uint4*)&sA[c][ty * 16 + 8];
            uint4 Bv = *(const uint4*)&sB[c][tx * 8];
            __half2 a2[8], b2[4];
            a2[0] = *(__half2*)&A0.x; a2[1] = *(__half2*)&A0.y;
            a2[2] = *(__half2*)&A0.z; a2[3] = *(__half2*)&A0.w;
            a2[4] = *(__half2*)&A1.x; a2[5] = *(__half2*)&A1.y;
            a2[6] = *(__half2*)&A1.z; a2[7] = *(__half2*)&A1.w;
            b2[0] = *(__half2*)&Bv.x; b2[1] = *(__half2*)&Bv.y;
            b2[2] = *(__half2*)&Bv.z; b2[3] = *(__half2*)&Bv.w;
#pragma unroll
            for (int i = 0; i < 8; ++i) {
#pragma unroll
                for (int jp = 0; jp < 4; ++jp) {
                    // HFMA2 (fma) + HMNMX2 relu (alu) + HADD2 (fma)
                    __half2 t = __hfma2(a2[i], b2[jp], mab2[i][jp]);
                    hacc[i] = __hadd2(hacc[i], __hmax2(t, hz));
                }
            }
        }

        // promote chunk accumulators to fp32 (pairwise into 4 accs)
#pragma unroll
        for (int i = 0; i < 8; i += 2) {
            __half2 hsum = __hadd2(hacc[i], hacc[i + 1]);   // <=64, fp16-safe
            facc[i >> 1] += __low2float(hsum) + __high2float(hsum);
        }
    }

    // Deterministic block reduction.
    float tsum = facc[0] + facc[1] + facc[2] + facc[3];
#pragma unroll
    for (int off = 16; off > 0; off >>= 1)
        tsum += __shfl_down_sync(0xFFFFFFFFu, tsum, off);

    __shared__ float wred[8];
    if ((tid & 31) == 0) wred[tid >> 5] = tsum;
    __syncthreads();

    // Publish partial, then elect the last-finishing CTA to do the final sum.
    __shared__ bool amLast;
    if (tid == 0) {
        float s = 0.0f;
#pragma unroll
        for (int w = 0; w < 8; ++w) s += wred[w];
        const int part = ((sl * CS + cblk) * (NT * NT)) + tile;
        g_part[part] = s;
        __threadfence();
        unsigned ticket = atomicAdd(&g_ctr, 1u);
        amLast = (ticket == NCTA - 1);
    }
    __syncthreads();

    if (amLast) {
        // Fixed-order deterministic final reduce over all 2048 partials.
        double s = 0.0;
#pragma unroll
        for (int k = 0; k < NCTA / 256; ++k)
            s += (double)g_part[tid + k * 256];
#pragma unroll
        for (int off = 16; off > 0; off >>= 1)
            s += __shfl_down_sync(0xFFFFFFFFu, s, off);
        __shared__ double dw[8];
        if ((tid & 31) == 0) dw[tid >> 5] = s;
        __syncthreads();
        if (tid == 0) {
            double tot = 0.0;
#pragma unroll
            for (int w = 0; w < 8; ++w) tot += dw[w];
            out[0] = (float)(tot / (double)(R_ * B_));
            g_ctr = 0;   // reset for next graph replay
        }
    }
}

extern "C" void kernel_launch(void* const* d_in, const int* in_sizes, int n_in,
                              void* d_out, int out_size) {
    const float* logits = (const float*)d_in[0];
    const int*   masks  = (const int*)d_in[1];
    float*       out    = (float*)d_out;

    sigmoid_mask_kernel<<<(B_ * N_ * N_ + 255) / 256, 256>>>(logits, masks);

    dim3 g2(NT * NT, CS, S_);
    trans_relu_kernel<<<g2, 256>>>(out);
}

// round 6
// speedup vs baseline: 2.1173x; 1.0786x over previous
#include <cuda_runtime.h>
#include <cuda_fp16.h>
#include <cstdint>

// LogicalConsistencyLoss: out = sum_{s,a,b,c} relu(M_ab - M_ac*M_bc) / (R*B)
// where M = fp16(sigmoid(logits)) * mask_a * mask_b per (batch,relation) slice.
// R6: fused relu into HFMA2 (__hfma2_relu) -> alu pipe freed;
//     single-stage smem (all 32 c's) -> 1 sync instead of 8.

#define B_ 2
#define N_ 512
#define R_ 4
#define S_ (B_ * R_)                   // 8 slices
#define NT (N_ / 128)                  // 4 tiles per dim
#define CS 16                          // c-split: 32 c's per CTA
#define NCTA (NT * NT * CS * S_)       // 2048 cubic CTAs / partials

__device__ __half    g_relh[S_ * N_ * N_];   // 4 MB scratch (L2-resident)
__device__ float     g_part[NCTA];
__device__ unsigned  g_ctr;                  // zero-init; reset by last CTA

// ---------------- Pass 1: sigmoid + mask -> fp16, de-interleave R ----------------
__global__ void sigmoid_mask_kernel(const float* __restrict__ logits,
                                    const int*   __restrict__ masks) {
    int idx = blockIdx.x * blockDim.x + threadIdx.x;  // over B*N*N
    if (idx >= B_ * N_ * N_) return;
    int b   = idx / (N_ * N_);
    int rem = idx - b * (N_ * N_);
    int i   = rem / N_;
    int j   = rem - i * N_;
    float mm = (masks[b * N_ + i] > 0 && masks[b * N_ + j] > 0) ? 1.0f : 0.0f;
    float4 v = ((const float4*)logits)[idx];  // 4 relations of one (b,i,j)
    float p0 = __fdividef(mm, 1.0f + __expf(-v.x));
    float p1 = __fdividef(mm, 1.0f + __expf(-v.y));
    float p2 = __fdividef(mm, 1.0f + __expf(-v.z));
    float p3 = __fdividef(mm, 1.0f + __expf(-v.w));
    g_relh[(b * R_ + 0) * N_ * N_ + rem] = __float2half(p0);
    g_relh[(b * R_ + 1) * N_ * N_ + rem] = __float2half(p1);
    g_relh[(b * R_ + 2) * N_ * N_ + rem] = __float2half(p2);
    g_relh[(b * R_ + 3) * N_ * N_ + rem] = __float2half(p3);
}

// ---------------- Pass 2: cubic relu contraction + fused final reduce ----------
// Grid: x = (a,b) tile (16), y = c-split (16), z = slice (8). 256 threads.
// Thread: 8x8 fp16 M_ab tile as 8x4 half2 regs; 8 half2 accs -> 4 f32.
__global__ void __launch_bounds__(256, 3)
trans_relu_kernel(float* __restrict__ out) {
    const int tile = blockIdx.x;      // 0..15
    const int cblk = blockIdx.y;      // 0..15
    const int sl   = blockIdx.z;      // 0..7
    const __half* __restrict__ M = g_relh + sl * N_ * N_;

    const int a0 = (tile / NT) * 128;
    const int b0 = (tile % NT) * 128;
    const int c0 = cblk * (N_ / CS);  // 32 c's per CTA

    const int tid = threadIdx.x;
    const int tx  = tid & 15;         // b sub-tile
    const int ty  = tid >> 4;         // a sub-tile

    // All 32 c's staged once.
    // sA holds NEGATED + DUPLICATED values: sA[c][2a]=sA[c][2a+1] = -M[a0+a][c]
    // so uint4 LDS yields 4 ready {-a,-a} half2 broadcast pairs.
    __shared__ __align__(16) __half sA[32][256];   // 16 KB
    __shared__ __align__(16) __half sB[32][128];   //  8 KB

    // 8x8 M_ab tile packed as half2 (j,j+1) pairs: 32 regs.
    __half2 mab2[8][4];
#pragma unroll
    for (int i = 0; i < 8; ++i) {
        uint4 q = *(const uint4*)(M + (a0 + ty * 8 + i) * N_ + b0 + tx * 8);
        mab2[i][0] = *(__half2*)&q.x; mab2[i][1] = *(__half2*)&q.y;
        mab2[i][2] = *(__half2*)&q.z; mab2[i][3] = *(__half2*)&q.w;
    }

    // Stage: each thread loads 32 c-values of one A-row or one B-row.
    {
        const int  sr  = tid & 127;
        const bool isB = tid >= 128;
        const __half* rowp = M + ((isB ? b0 : a0) + sr) * N_ + c0;
        uint4 v0 = ((const uint4*)rowp)[0];
        uint4 v1 = ((const uint4*)rowp)[1];
        uint4 v2 = ((const uint4*)rowp)[2];
        uint4 v3 = ((const uint4*)rowp)[3];
        __half h[32];
        *(uint4*)&h[0]  = v0; *(uint4*)&h[8]  = v1;
        *(uint4*)&h[16] = v2; *(uint4*)&h[24] = v3;
        if (!isB) {
#pragma unroll
            for (int k = 0; k < 32; ++k) {
                __half2 p = __half2half2(__hneg(h[k]));
                *(uint32_t*)&sA[k][2 * sr] = *(uint32_t*)&p;
            }
        } else {
#pragma unroll
            for (int k = 0; k < 32; ++k) sB[k][sr] = h[k];
        }
    }
    __syncthreads();

    float facc[4];
#pragma unroll
    for (int p = 0; p < 4; ++p) facc[p] = 0.0f;

    // Mainloop: 4 blocks of 8 c's; fp32 promotion between blocks.
#pragma unroll
    for (int cb = 0; cb < 32; cb += 8) {
        __half2 hacc[8];                   // per-i accs: <=32 terms each
#pragma unroll
        for (int i = 0; i < 8; ++i) hacc[i] = __float2half2_rn(0.0f);

#pragma unroll
        for (int cc = 0; cc < 8; ++cc) {
            const int c = cb + cc;
            uint4 A0 = *(const uint4*)&sA[c][ty * 16];
            uint4 A1 = *(const uint4*)&sA[c][ty * 16 + 8];
            uint4 Bv = *(const uint4*)&sB[c][tx * 8];
            __half2 a2[8], b2[4];
            a2[0] = *(__half2*)&A0.x; a2[1] = *(__half2*)&A0.y;
            a2[2] = *(__half2*)&A0.z; a2[3] = *(__half2*)&A0.w;
            a2[4] = *(__half2*)&A1.x; a2[5] = *(__half2*)&A1.y;
            a2[6] = *(__half2*)&A1.z; a2[7] = *(__half2*)&A1.w;
            b2[0] = *(__half2*)&Bv.x; b2[1] = *(__half2*)&Bv.y;
            b2[2] = *(__half2*)&Bv.z; b2[3] = *(__half2*)&Bv.w;
#pragma unroll
            for (int i = 0; i < 8; ++i) {
#pragma unroll
                for (int jp = 0; jp < 4; ++jp) {
                    // fma.rn.relu.f16x2: relu fused into HFMA2 -> 2 fma-pipe
                    // instrs per half2, zero alu-pipe work.
                    hacc[i] = __hadd2(hacc[i],
                                      __hfma2_relu(a2[i], b2[jp], mab2[i][jp]));
                }
            }
        }

        // promote block accumulators to fp32 (pairwise into 4 accs)
#pragma unroll
        for (int i = 0; i < 8; i += 2) {
            __half2 hsum = __hadd2(hacc[i], hacc[i + 1]);   // <=64, fp16-safe
            facc[i >> 1] += __low2float(hsum) + __high2float(hsum);
        }
    }

    // Deterministic block reduction.
    float tsum = facc[0] + facc[1] + facc[2] + facc[3];
#pragma unroll
    for (int off = 16; off > 0; off >>= 1)
        tsum += __shfl_down_sync(0xFFFFFFFFu, tsum, off);

    __shared__ float wred[8];
    if ((tid & 31) == 0) wred[tid >> 5] = tsum;
    __syncthreads();

    // Publish partial, then elect the last-finishing CTA to do the final sum.
    __shared__ bool amLast;
    if (tid == 0) {
        float s = 0.0f;
#pragma unroll
        for (int w = 0; w < 8; ++w) s += wred[w];
        const int part = ((sl * CS + cblk) * (NT * NT)) + tile;
        g_part[part] = s;
        __threadfence();
        unsigned ticket = atomicAdd(&g_ctr, 1u);
        amLast = (ticket == NCTA - 1);
    }
    __syncthreads();

    if (amLast) {
        // Fixed-order deterministic final reduce over all 2048 partials.
        double s = 0.0;
#pragma unroll
        for (int k = 0; k < NCTA / 256; ++k)
            s += (double)g_part[tid + k * 256];
#pragma unroll
        for (int off = 16; off > 0; off >>= 1)
            s += __shfl_down_sync(0xFFFFFFFFu, s, off);
        __shared__ double dw[8];
        if ((tid & 31) == 0) dw[tid >> 5] = s;
        __syncthreads();
        if (tid == 0) {
            double tot = 0.0;
#pragma unroll
            for (int w = 0; w < 8; ++w) tot += dw[w];
            out[0] = (float)(tot / (double)(R_ * B_));
            g_ctr = 0;   // reset for next graph replay
        }
    }
}

extern "C" void kernel_launch(void* const* d_in, const int* in_sizes, int n_in,
                              void* d_out, int out_size) {
    const float* logits = (const float*)d_in[0];
    const int*   masks  = (const int*)d_in[1];
    float*       out    = (float*)d_out;

    sigmoid_mask_kernel<<<(B_ * N_ * N_ + 255) / 256, 256>>>(logits, masks);

    dim3 g2(NT * NT, CS, S_);
    trans_relu_kernel<<<g2, 256>>>(out);
}